// round 13
// baseline (speedup 1.0000x reference)
#include <cuda_runtime.h>
#include <cstdint>

#define DM 1024
#define NH 16
#define DH 64
#define BB 2
#define SS 2048
#define MT (BB*SS)

// Scratch (device globals; no allocation allowed anywhere)
__device__ float g_qh[MT*DM];    // [B,H,S,DH]
__device__ float g_kh[MT*DM];    // [B,H,S,DH]
__device__ float g_vt[MT*DM];    // [B,H,DH,S]  (V transposed)
__device__ float g_at[MT*DM];    // merged-head attention output [B,S,DM]
__device__ float g_wT[4*DM*DM];  // W^T for wq,wk,wv,wo

// ---------------------------------------------------------------------------
__device__ __forceinline__ unsigned tf32r(float x) {
    unsigned u;
    asm("cvt.rna.tf32.f32 %0, %1;" : "=r"(u) : "f"(x));
    return u;
}
__device__ __forceinline__ unsigned tf32u(unsigned raw) {
    return tf32r(__uint_as_float(raw));
}
__device__ __forceinline__ void mma_tf32(float c[4], const unsigned a[4],
                                         const unsigned b[2]) {
    asm volatile(
        "mma.sync.aligned.m16n8k8.row.col.f32.tf32.tf32.f32 "
        "{%0,%1,%2,%3}, {%4,%5,%6,%7}, {%8,%9}, {%0,%1,%2,%3};"
        : "+f"(c[0]), "+f"(c[1]), "+f"(c[2]), "+f"(c[3])
        : "r"(a[0]), "r"(a[1]), "r"(a[2]), "r"(a[3]), "r"(b[0]), "r"(b[1]));
}

#define CP_A16(dst, src) \
    asm volatile("cp.async.cg.shared.global [%0], [%1], 16;" :: "r"(dst), "l"(src))
#define CP_COMMIT() asm volatile("cp.async.commit_group;" ::: "memory")
#define CP_WAIT1()  asm volatile("cp.async.wait_group 1;" ::: "memory")
#define CP_WAIT0()  asm volatile("cp.async.wait_group 0;" ::: "memory")

struct GA { const float* A; const float* W; const float* bias; float* out; int mode; };
struct G3 { GA g[3]; };

// ---------------------------------------------------------------------------
// Weight transpose: wt[n*DM + k] = w[k*DM + n]
// ---------------------------------------------------------------------------
__global__ __launch_bounds__(256) void transp(const float* __restrict__ w,
                                              float* __restrict__ wt)
{
    __shared__ float tl[32][33];
    int x = blockIdx.x * 32 + threadIdx.x;
    int y = blockIdx.y * 32 + threadIdx.y;
    #pragma unroll
    for (int j = 0; j < 32; j += 8)
        tl[threadIdx.y + j][threadIdx.x] = w[(size_t)(y + j) * DM + x];
    __syncthreads();
    int x2 = blockIdx.y * 32 + threadIdx.x;
    int y2 = blockIdx.x * 32 + threadIdx.y;
    #pragma unroll
    for (int j = 0; j < 32; j += 8)
        wt[(size_t)(y2 + j) * DM + x2] = tl[threadIdx.x][threadIdx.y + j];
}

// ---------------------------------------------------------------------------
// TF32 GEMM, double-buffered, conflict-free padded row-major smem.
// (unchanged from R12 — proven)
// ---------------------------------------------------------------------------
__global__ __launch_bounds__(128, 2) void gemm_tf32(G3 P)
{
    __shared__ __align__(16) unsigned As[2][2560];   // [buf][row128][20]
    __shared__ __align__(16) unsigned Bs[2][2560];   // [buf][nrow128][20]

    const GA ga = P.g[blockIdx.z];
    const int tid = threadIdx.x, lane = tid & 31, wid = tid >> 5;
    const int g = lane >> 2, t = lane & 3;
    const int bm = blockIdx.y * 128, bn = blockIdx.x * 128;

    const int sr = tid >> 2, skq = (tid & 3) << 2;
    const float* Aptr = ga.A + (size_t)(bm + sr) * DM + skq;
    const float* Bptr = ga.W + (size_t)(bn + sr) * DM + skq;
    const unsigned stBase = sr * 20 + skq;

    const int wm = (wid >> 1) * 64, wn = (wid & 1) * 64;
    const unsigned aB = (wm + g) * 20 + t;
    const unsigned bB = (wn + g) * 20 + t;

    float acc[4][8][4];
    #pragma unroll
    for (int im = 0; im < 4; im++)
        #pragma unroll
        for (int jn = 0; jn < 8; jn++)
            #pragma unroll
            for (int r = 0; r < 4; r++) acc[im][jn][r] = 0.f;

    float4 ra[4], rb[4];

#define G_LOAD(K0) do {                                                     \
    _Pragma("unroll")                                                       \
    for (int p = 0; p < 4; p++) {                                           \
        ra[p] = *(const float4*)(Aptr + (size_t)p * 32 * DM + (K0));        \
        rb[p] = *(const float4*)(Bptr + (size_t)p * 32 * DM + (K0));        \
    }                                                                       \
} while (0)

#define G_STORE(BUF) do {                                                   \
    _Pragma("unroll")                                                       \
    for (int p = 0; p < 4; p++) {                                           \
        uint4 ua = make_uint4(tf32r(ra[p].x), tf32r(ra[p].y),               \
                              tf32r(ra[p].z), tf32r(ra[p].w));              \
        *(uint4*)&As[BUF][stBase + p * 640] = ua;                           \
        uint4 ub = make_uint4(tf32r(rb[p].x), tf32r(rb[p].y),               \
                              tf32r(rb[p].z), tf32r(rb[p].w));              \
        *(uint4*)&Bs[BUF][stBase + p * 640] = ub;                           \
    }                                                                       \
} while (0)

    G_LOAD(0);
    G_STORE(0);
    __syncthreads();

    for (int kc = 0; kc < 64; kc++) {
        if (kc < 63) G_LOAD((kc + 1) * 16);
        const int buf = kc & 1;
        #pragma unroll
        for (int kt = 0; kt < 2; kt++) {
            unsigned a[4][4], b[8][2];
            #pragma unroll
            for (int im = 0; im < 4; im++) {
                unsigned base = aB + im * 320 + kt * 8;
                a[im][0] = As[buf][base];
                a[im][1] = As[buf][base + 160];
                a[im][2] = As[buf][base + 4];
                a[im][3] = As[buf][base + 164];
            }
            #pragma unroll
            for (int jn = 0; jn < 8; jn++) {
                unsigned base = bB + jn * 160 + kt * 8;
                b[jn][0] = Bs[buf][base];
                b[jn][1] = Bs[buf][base + 4];
            }
            #pragma unroll
            for (int im = 0; im < 4; im++)
                #pragma unroll
                for (int jn = 0; jn < 8; jn++)
                    mma_tf32(acc[im][jn], a[im], b[jn]);
        }
        if (kc < 63) G_STORE((kc + 1) & 1);
        __syncthreads();
    }

    #pragma unroll
    for (int im = 0; im < 4; im++) {
        int r0 = bm + wm + im * 16 + g;
        int r1 = r0 + 8;
        #pragma unroll
        for (int jn = 0; jn < 8; jn++) {
            int col = bn + wn + jn * 8 + t * 2;
            float b0 = ga.bias[col], b1 = ga.bias[col + 1];
            float v00 = acc[im][jn][0] + b0, v01 = acc[im][jn][1] + b1;
            float v10 = acc[im][jn][2] + b0, v11 = acc[im][jn][3] + b1;
            if (ga.mode == 0) {
                float* p0 = ga.out + (size_t)r0 * DM + col;
                float* p1 = ga.out + (size_t)r1 * DM + col;
                p0[0] = v00; p0[1] = v01;
                p1[0] = v10; p1[1] = v11;
            } else {
                int h = col >> 6, d = col & 63;
                int b_0 = r0 >> 11, s_0 = r0 & (SS - 1);
                int b_1 = r1 >> 11, s_1 = r1 & (SS - 1);
                if (ga.mode == 1) {
                    float* p0 = ga.out + (((size_t)(b_0 * NH + h)) * SS + s_0) * DH + d;
                    float* p1 = ga.out + (((size_t)(b_1 * NH + h)) * SS + s_1) * DH + d;
                    p0[0] = v00; p0[1] = v01;
                    p1[0] = v10; p1[1] = v11;
                } else {
                    float* base0 = ga.out + ((size_t)(b_0 * NH + h) * DH + d) * SS + s_0;
                    float* base1 = ga.out + ((size_t)(b_1 * NH + h) * DH + d) * SS + s_1;
                    base0[0] = v00; base0[SS] = v01;
                    base1[0] = v10; base1[SS] = v11;
                }
            }
        }
    }
#undef G_LOAD
#undef G_STORE
}

// ---------------------------------------------------------------------------
// TF32 flash attention, cp.async double-buffered K/V (raw f32 in smem,
// tf32 conversion at fragment-load). Conflict-free stride-68 layouts.
// Block = 128 q x (head, batch), 128 threads = 4 warps, warp = 32q x 64k.
// ---------------------------------------------------------------------------
__global__ __launch_bounds__(128) void attn_tf32(const float* __restrict__ mask,
                                                 float* __restrict__ outp)
{
    extern __shared__ __align__(16) unsigned smu[];
    // Ps:  [0, 8704)           Q stage (tf32) then per-warp P buffer
    // Ks:  [8704 + buf*4352)   K tile, raw f32, [key64][68]
    // Vts: [17408 + buf*4352)  V^T tile, raw f32, [d64][68]
    unsigned* Ps = smu;

    const int tid  = threadIdx.x;
    const int lane = tid & 31, wid = tid >> 5;
    const int g = lane >> 2, t = lane & 3;
    const int q0 = blockIdx.x * 128;
    const int h  = blockIdx.y;
    const int b  = blockIdx.z;
    const float* Qg  = g_qh + (size_t)(b * NH + h) * SS * DH;
    const float* Kg  = g_kh + (size_t)(b * NH + h) * SS * DH;
    const float* Vtg = g_vt + (size_t)(b * NH + h) * DH * SS;

    const unsigned smb = (unsigned)__cvta_generic_to_shared(smu);
    const int s_cq = (tid & 15) << 2, s_rr = tid >> 4;

    float o[2][8][4];
    #pragma unroll
    for (int im = 0; im < 2; im++)
        #pragma unroll
        for (int j = 0; j < 8; j++)
            #pragma unroll
            for (int r = 0; r < 4; r++) o[im][j][r] = 0.f;
    float mrow[2][2] = {{-1e30f, -1e30f}, {-1e30f, -1e30f}};
    float lrow[2][2] = {{0.f, 0.f}, {0.f, 0.f}};

    // Kick off tile 0's K/V copies before doing Q staging work
    {
        const unsigned kb = smb + (8704u) * 4, vb = smb + (17408u) * 4;
        #pragma unroll
        for (int i = 0; i < 8; i++) {
            int row = s_rr + i * 8;
            CP_A16(kb + (row * 68 + s_cq) * 4, Kg + (size_t)row * DH + s_cq);
            CP_A16(vb + (row * 68 + s_cq) * 4, Vtg + (size_t)row * SS + s_cq);
        }
        CP_COMMIT();
    }

    // Stage Q tile (128 x 64) row-major stride 68 (tf32)
    #pragma unroll
    for (int i = 0; i < 16; i++) {
        int q = s_rr + i * 8;
        float4 v = *(const float4*)(Qg + (size_t)(q0 + q) * DH + s_cq);
        uint4 u = make_uint4(tf32r(v.x), tf32r(v.y), tf32r(v.z), tf32r(v.w));
        *(uint4*)&Ps[q * 68 + s_cq] = u;
    }
    __syncthreads();

    // Hoist warp's Q fragments
    unsigned qa[2][8][4];
    {
        const unsigned qB = (wid * 32 + g) * 68 + t;
        #pragma unroll
        for (int ktd = 0; ktd < 8; ktd++)
            #pragma unroll
            for (int im = 0; im < 2; im++) {
                unsigned base = qB + im * 1088 + ktd * 8;
                qa[im][ktd][0] = Ps[base];
                qa[im][ktd][1] = Ps[base + 544];
                qa[im][ktd][2] = Ps[base + 4];
                qa[im][ktd][3] = Ps[base + 548];
            }
    }

    const unsigned pW = wid * 2176;
    const unsigned kB = g * 68 + t;

    for (int it = 0; it < SS / 64; it++) {
        // Issue next tile's copies into the other buffer
        if (it + 1 < SS / 64) {
            const int nb = (it + 1) & 1, k0n = (it + 1) * 64;
            const unsigned kb = smb + (8704u + nb * 4352u) * 4;
            const unsigned vb = smb + (17408u + nb * 4352u) * 4;
            #pragma unroll
            for (int i = 0; i < 8; i++) {
                int row = s_rr + i * 8;
                CP_A16(kb + (row * 68 + s_cq) * 4,
                       Kg + (size_t)(k0n + row) * DH + s_cq);
                CP_A16(vb + (row * 68 + s_cq) * 4,
                       Vtg + (size_t)row * SS + k0n + s_cq);
            }
            CP_COMMIT();
            CP_WAIT1();
        } else {
            CP_WAIT0();
        }
        __syncthreads();

        const int buf = it & 1, k0 = it * 64;
        const unsigned* Ksb  = smu + 8704 + buf * 4352;
        const unsigned* Vtsb = smu + 17408 + buf * 4352;

        // Scores: 32q x 64k per warp (Q regs, K raw->tf32 at load)
        float s[2][8][4];
        #pragma unroll
        for (int im = 0; im < 2; im++)
            #pragma unroll
            for (int j = 0; j < 8; j++)
                #pragma unroll
                for (int r = 0; r < 4; r++) s[im][j][r] = 0.f;

        #pragma unroll
        for (int ktd = 0; ktd < 8; ktd++) {
            #pragma unroll
            for (int nt = 0; nt < 8; nt++) {
                unsigned bk[2];
                unsigned base = kB + nt * 544 + ktd * 8;
                bk[0] = tf32u(Ksb[base]);
                bk[1] = tf32u(Ksb[base + 4]);
                mma_tf32(s[0][nt], qa[0][ktd], bk);
                mma_tf32(s[1][nt], qa[1][ktd], bk);
            }
        }

        // Scale + mask
        #pragma unroll
        for (int im = 0; im < 2; im++) {
            int r0 = q0 + wid * 32 + im * 16 + g;
            int r1 = r0 + 8;
            #pragma unroll
            for (int nt = 0; nt < 8; nt++) {
                int col = k0 + nt * 8 + t * 2;
                float2 mk0 = __ldg((const float2*)(mask + (size_t)r0 * SS + col));
                float2 mk1 = __ldg((const float2*)(mask + (size_t)r1 * SS + col));
                s[im][nt][0] = s[im][nt][0] * 0.125f - 1e9f * mk0.x;
                s[im][nt][1] = s[im][nt][1] * 0.125f - 1e9f * mk0.y;
                s[im][nt][2] = s[im][nt][2] * 0.125f - 1e9f * mk1.x;
                s[im][nt][3] = s[im][nt][3] * 0.125f - 1e9f * mk1.y;
            }
        }

        // Online softmax
        #pragma unroll
        for (int im = 0; im < 2; im++) {
            float mx0 = -1e30f, mx1 = -1e30f;
            #pragma unroll
            for (int nt = 0; nt < 8; nt++) {
                mx0 = fmaxf(mx0, fmaxf(s[im][nt][0], s[im][nt][1]));
                mx1 = fmaxf(mx1, fmaxf(s[im][nt][2], s[im][nt][3]));
            }
            mx0 = fmaxf(mx0, __shfl_xor_sync(0xffffffffu, mx0, 1));
            mx0 = fmaxf(mx0, __shfl_xor_sync(0xffffffffu, mx0, 2));
            mx1 = fmaxf(mx1, __shfl_xor_sync(0xffffffffu, mx1, 1));
            mx1 = fmaxf(mx1, __shfl_xor_sync(0xffffffffu, mx1, 2));

            float nm0 = fmaxf(mrow[im][0], mx0), nm1 = fmaxf(mrow[im][1], mx1);
            float al0 = __expf(mrow[im][0] - nm0), al1 = __expf(mrow[im][1] - nm1);
            float sum0 = 0.f, sum1 = 0.f;
            #pragma unroll
            for (int nt = 0; nt < 8; nt++) {
                float p0 = __expf(s[im][nt][0] - nm0);
                float p1 = __expf(s[im][nt][1] - nm0);
                float p2 = __expf(s[im][nt][2] - nm1);
                float p3 = __expf(s[im][nt][3] - nm1);
                s[im][nt][0] = p0; s[im][nt][1] = p1;
                s[im][nt][2] = p2; s[im][nt][3] = p3;
                sum0 += p0 + p1;
                sum1 += p2 + p3;
            }
            sum0 += __shfl_xor_sync(0xffffffffu, sum0, 1);
            sum0 += __shfl_xor_sync(0xffffffffu, sum0, 2);
            sum1 += __shfl_xor_sync(0xffffffffu, sum1, 1);
            sum1 += __shfl_xor_sync(0xffffffffu, sum1, 2);
            lrow[im][0] = lrow[im][0] * al0 + sum0;
            lrow[im][1] = lrow[im][1] * al1 + sum1;
            mrow[im][0] = nm0; mrow[im][1] = nm1;

            #pragma unroll
            for (int nt = 0; nt < 8; nt++) {
                o[im][nt][0] *= al0; o[im][nt][1] *= al0;
                o[im][nt][2] *= al1; o[im][nt][3] *= al1;
            }
        }

        // Store P (tf32) into warp's own band
        #pragma unroll
        for (int im = 0; im < 2; im++) {
            #pragma unroll
            for (int nt = 0; nt < 8; nt++) {
                unsigned idx = pW + (im * 16 + g) * 68 + nt * 8 + t * 2;
                uint2 p01 = make_uint2(tf32r(s[im][nt][0]), tf32r(s[im][nt][1]));
                *(uint2*)&Ps[idx] = p01;
                uint2 p23 = make_uint2(tf32r(s[im][nt][2]), tf32r(s[im][nt][3]));
                *(uint2*)&Ps[idx + 544] = p23;
            }
        }
        __syncwarp();

        // PV: A-frag of P, B = V^T (raw->tf32 at load)
        const unsigned pA = pW + g * 68 + t;
        #pragma unroll
        for (int ktk = 0; ktk < 8; ktk++) {
            unsigned ap[2][4];
            #pragma unroll
            for (int im = 0; im < 2; im++) {
                unsigned base = pA + im * 1088 + ktk * 8;
                ap[im][0] = Ps[base];
                ap[im][1] = Ps[base + 544];
                ap[im][2] = Ps[base + 4];
                ap[im][3] = Ps[base + 548];
            }
            #pragma unroll
            for (int ntd = 0; ntd < 8; ntd++) {
                unsigned bv[2];
                unsigned base = kB + ntd * 544 + ktk * 8;
                bv[0] = tf32u(Vtsb[base]);
                bv[1] = tf32u(Vtsb[base + 4]);
                mma_tf32(o[0][ntd], ap[0], bv);
                mma_tf32(o[1][ntd], ap[1], bv);
            }
        }
        __syncthreads();
    }

    // Epilogue: normalize + write merged-head layout
    #pragma unroll
    for (int im = 0; im < 2; im++) {
        float inv0 = 1.0f / lrow[im][0], inv1 = 1.0f / lrow[im][1];
        int r0 = q0 + wid * 32 + im * 16 + g;
        int r1 = r0 + 8;
        #pragma unroll
        for (int ntd = 0; ntd < 8; ntd++) {
            int col = h * DH + ntd * 8 + t * 2;
            float2 v0 = make_float2(o[im][ntd][0] * inv0, o[im][ntd][1] * inv0);
            float2 v1 = make_float2(o[im][ntd][2] * inv1, o[im][ntd][3] * inv1);
            *(float2*)(outp + ((size_t)b * SS + r0) * DM + col) = v0;
            *(float2*)(outp + ((size_t)b * SS + r1) * DM + col) = v1;
        }
    }
}

// ---------------------------------------------------------------------------
extern "C" void kernel_launch(void* const* d_in, const int* in_sizes, int n_in,
                              void* d_out, int out_size)
{
    const float* q    = (const float*)d_in[0];
    const float* k    = (const float*)d_in[1];
    const float* v    = (const float*)d_in[2];
    const float* mask = (const float*)d_in[3];
    const float* wq   = (const float*)d_in[4];
    const float* bq   = (const float*)d_in[5];
    const float* wk   = (const float*)d_in[6];
    const float* bk   = (const float*)d_in[7];
    const float* wv   = (const float*)d_in[8];
    const float* bv   = (const float*)d_in[9];
    const float* wo   = (const float*)d_in[10];
    const float* bo   = (const float*)d_in[11];

    float *qh, *kh, *vt, *at, *wT;
    cudaGetSymbolAddress((void**)&qh, g_qh);
    cudaGetSymbolAddress((void**)&kh, g_kh);
    cudaGetSymbolAddress((void**)&vt, g_vt);
    cudaGetSymbolAddress((void**)&at, g_at);
    cudaGetSymbolAddress((void**)&wT, g_wT);

    const int attn_smem = (8704 + 2 * 4352 + 2 * 4352) * (int)sizeof(unsigned); // ~104 KB
    cudaFuncSetAttribute(attn_tf32, cudaFuncAttributeMaxDynamicSharedMemorySize,
                         attn_smem);

    // Transpose weights once per call
    dim3 tb(32, 8), tg(32, 32);
    transp<<<tg, tb>>>(wq, wT + 0 * DM * DM);
    transp<<<tg, tb>>>(wk, wT + 1 * DM * DM);
    transp<<<tg, tb>>>(wv, wT + 2 * DM * DM);
    transp<<<tg, tb>>>(wo, wT + 3 * DM * DM);

    // Fused Q/K/V projections (V written transposed)
    G3 pqkv;
    pqkv.g[0] = GA{q, wT + 0 * DM * DM, bq, qh, 1};
    pqkv.g[1] = GA{k, wT + 1 * DM * DM, bk, kh, 1};
    pqkv.g[2] = GA{v, wT + 2 * DM * DM, bv, vt, 2};
    dim3 gqkv(DM / 128, MT / 128, 3);
    gemm_tf32<<<gqkv, 128>>>(pqkv);

    dim3 ga(SS / 128, NH, BB);
    attn_tf32<<<ga, 128, attn_smem>>>(mask, at);

    G3 po;
    po.g[0] = GA{at, wT + 3 * DM * DM, bo, (float*)d_out, 0};
    po.g[1] = po.g[0];
    po.g[2] = po.g[0];
    dim3 go(DM / 128, MT / 128, 1);
    gemm_tf32<<<go, 128>>>(po);
}

// round 14
// speedup vs baseline: 1.5118x; 1.5118x over previous
#include <cuda_runtime.h>
#include <cstdint>

#define DM 1024
#define NH 16
#define DH 64
#define BB 2
#define SS 2048
#define MT (BB*SS)

// Scratch (device globals; no allocation allowed anywhere)
__device__ float g_qh[MT*DM];    // [B,H,S,DH]
__device__ float g_kh[MT*DM];    // [B,H,S,DH]
__device__ float g_vt[MT*DM];    // [B,H,DH,S]  (V transposed)
__device__ float g_at[MT*DM];    // merged-head attention output [B,S,DM]
__device__ float g_wT[4*DM*DM];  // W^T for wq,wk,wv,wo

// ---------------------------------------------------------------------------
__device__ __forceinline__ unsigned tf32r(float x) {
    unsigned u;
    asm("cvt.rna.tf32.f32 %0, %1;" : "=r"(u) : "f"(x));
    return u;
}
__device__ __forceinline__ uint4 cvt4(float4 v) {
    return make_uint4(tf32r(v.x), tf32r(v.y), tf32r(v.z), tf32r(v.w));
}
__device__ __forceinline__ void mma_tf32(float c[4], const unsigned a[4],
                                         const unsigned b[2]) {
    asm volatile(
        "mma.sync.aligned.m16n8k8.row.col.f32.tf32.tf32.f32 "
        "{%0,%1,%2,%3}, {%4,%5,%6,%7}, {%8,%9}, {%0,%1,%2,%3};"
        : "+f"(c[0]), "+f"(c[1]), "+f"(c[2]), "+f"(c[3])
        : "r"(a[0]), "r"(a[1]), "r"(a[2]), "r"(a[3]), "r"(b[0]), "r"(b[1]));
}

#define CP_A16(dst, src) \
    asm volatile("cp.async.cg.shared.global [%0], [%1], 16;" :: "r"(dst), "l"(src))
#define CP_COMMIT() asm volatile("cp.async.commit_group;" ::: "memory")
#define CP_WAIT1()  asm volatile("cp.async.wait_group 1;" ::: "memory")
#define CP_WAIT0()  asm volatile("cp.async.wait_group 0;" ::: "memory")

struct GA { const float* A; const float* W; const float* bias; float* out; int mode; };
struct G3 { GA g[3]; };

// ---------------------------------------------------------------------------
// Fused weight transposes: wt[z][n*DM + k] = w_z[k*DM + n]
// ---------------------------------------------------------------------------
__global__ __launch_bounds__(256) void transp4(const float* __restrict__ w0,
                                               const float* __restrict__ w1,
                                               const float* __restrict__ w2,
                                               const float* __restrict__ w3,
                                               float* __restrict__ wt)
{
    __shared__ float tl[32][33];
    const float* w = (blockIdx.z == 0) ? w0 : (blockIdx.z == 1) ? w1
                    : (blockIdx.z == 2) ? w2 : w3;
    float* dst = wt + (size_t)blockIdx.z * DM * DM;
    int x = blockIdx.x * 32 + threadIdx.x;
    int y = blockIdx.y * 32 + threadIdx.y;
    #pragma unroll
    for (int j = 0; j < 32; j += 8)
        tl[threadIdx.y + j][threadIdx.x] = w[(size_t)(y + j) * DM + x];
    __syncthreads();
    int x2 = blockIdx.y * 32 + threadIdx.x;
    int y2 = blockIdx.x * 32 + threadIdx.y;
    #pragma unroll
    for (int j = 0; j < 32; j += 8)
        dst[(size_t)(y2 + j) * DM + x2] = tl[threadIdx.x][threadIdx.y + j];
}

// ---------------------------------------------------------------------------
// TF32 GEMM, double-buffered, conflict-free padded row-major smem.
// (unchanged from R12 — proven)
// ---------------------------------------------------------------------------
__global__ __launch_bounds__(128, 2) void gemm_tf32(G3 P)
{
    __shared__ __align__(16) unsigned As[2][2560];   // [buf][row128][20]
    __shared__ __align__(16) unsigned Bs[2][2560];   // [buf][nrow128][20]

    const GA ga = P.g[blockIdx.z];
    const int tid = threadIdx.x, lane = tid & 31, wid = tid >> 5;
    const int g = lane >> 2, t = lane & 3;
    const int bm = blockIdx.y * 128, bn = blockIdx.x * 128;

    const int sr = tid >> 2, skq = (tid & 3) << 2;
    const float* Aptr = ga.A + (size_t)(bm + sr) * DM + skq;
    const float* Bptr = ga.W + (size_t)(bn + sr) * DM + skq;
    const unsigned stBase = sr * 20 + skq;

    const int wm = (wid >> 1) * 64, wn = (wid & 1) * 64;
    const unsigned aB = (wm + g) * 20 + t;
    const unsigned bB = (wn + g) * 20 + t;

    float acc[4][8][4];
    #pragma unroll
    for (int im = 0; im < 4; im++)
        #pragma unroll
        for (int jn = 0; jn < 8; jn++)
            #pragma unroll
            for (int r = 0; r < 4; r++) acc[im][jn][r] = 0.f;

    float4 ra[4], rb[4];

#define G_LOAD(K0) do {                                                     \
    _Pragma("unroll")                                                       \
    for (int p = 0; p < 4; p++) {                                           \
        ra[p] = *(const float4*)(Aptr + (size_t)p * 32 * DM + (K0));        \
        rb[p] = *(const float4*)(Bptr + (size_t)p * 32 * DM + (K0));        \
    }                                                                       \
} while (0)

#define G_STORE(BUF) do {                                                   \
    _Pragma("unroll")                                                       \
    for (int p = 0; p < 4; p++) {                                           \
        *(uint4*)&As[BUF][stBase + p * 640] = cvt4(ra[p]);                  \
        *(uint4*)&Bs[BUF][stBase + p * 640] = cvt4(rb[p]);                  \
    }                                                                       \
} while (0)

    G_LOAD(0);
    G_STORE(0);
    __syncthreads();

    for (int kc = 0; kc < 64; kc++) {
        if (kc < 63) G_LOAD((kc + 1) * 16);
        const int buf = kc & 1;
        #pragma unroll
        for (int kt = 0; kt < 2; kt++) {
            unsigned a[4][4], b[8][2];
            #pragma unroll
            for (int im = 0; im < 4; im++) {
                unsigned base = aB + im * 320 + kt * 8;
                a[im][0] = As[buf][base];
                a[im][1] = As[buf][base + 160];
                a[im][2] = As[buf][base + 4];
                a[im][3] = As[buf][base + 164];
            }
            #pragma unroll
            for (int jn = 0; jn < 8; jn++) {
                unsigned base = bB + jn * 160 + kt * 8;
                b[jn][0] = Bs[buf][base];
                b[jn][1] = Bs[buf][base + 4];
            }
            #pragma unroll
            for (int im = 0; im < 4; im++)
                #pragma unroll
                for (int jn = 0; jn < 8; jn++)
                    mma_tf32(acc[im][jn], a[im], b[jn]);
        }
        if (kc < 63) G_STORE((kc + 1) & 1);
        __syncthreads();
    }

    #pragma unroll
    for (int im = 0; im < 4; im++) {
        int r0 = bm + wm + im * 16 + g;
        int r1 = r0 + 8;
        #pragma unroll
        for (int jn = 0; jn < 8; jn++) {
            int col = bn + wn + jn * 8 + t * 2;
            float b0 = ga.bias[col], b1 = ga.bias[col + 1];
            float v00 = acc[im][jn][0] + b0, v01 = acc[im][jn][1] + b1;
            float v10 = acc[im][jn][2] + b0, v11 = acc[im][jn][3] + b1;
            if (ga.mode == 0) {
                float* p0 = ga.out + (size_t)r0 * DM + col;
                float* p1 = ga.out + (size_t)r1 * DM + col;
                p0[0] = v00; p0[1] = v01;
                p1[0] = v10; p1[1] = v11;
            } else {
                int h = col >> 6, d = col & 63;
                int b_0 = r0 >> 11, s_0 = r0 & (SS - 1);
                int b_1 = r1 >> 11, s_1 = r1 & (SS - 1);
                if (ga.mode == 1) {
                    float* p0 = ga.out + (((size_t)(b_0 * NH + h)) * SS + s_0) * DH + d;
                    float* p1 = ga.out + (((size_t)(b_1 * NH + h)) * SS + s_1) * DH + d;
                    p0[0] = v00; p0[1] = v01;
                    p1[0] = v10; p1[1] = v11;
                } else {
                    float* base0 = ga.out + ((size_t)(b_0 * NH + h) * DH + d) * SS + s_0;
                    float* base1 = ga.out + ((size_t)(b_1 * NH + h) * DH + d) * SS + s_1;
                    base0[0] = v00; base0[SS] = v01;
                    base1[0] = v10; base1[SS] = v11;
                }
            }
        }
    }
#undef G_LOAD
#undef G_STORE
}

// ---------------------------------------------------------------------------
// TF32 flash attention. R12 compute structure (producer-side cvt, conflict-
// free stride-68 layouts) + cp.async double-buffered raw K/V with an
// in-place tf32 convert pass per tile. Block = 128 q, 4 warps x 32q.
// ---------------------------------------------------------------------------
#define KS0 8704
#define VS0 17408
#define ATT_SMEM_U32 (8704 + 2*4352 + 2*4352)   // 26112 u32 = 102 KB

__global__ __launch_bounds__(128) void attn_tf32(const float* __restrict__ mask,
                                                 float* __restrict__ outp)
{
    extern __shared__ __align__(16) unsigned smu[];
    unsigned* Ps = smu;              // Q stage (tf32), then per-warp P buffer

    const int tid  = threadIdx.x;
    const int lane = tid & 31, wid = tid >> 5;
    const int g = lane >> 2, t = lane & 3;
    const int q0 = blockIdx.x * 128;
    const int h  = blockIdx.y;
    const int b  = blockIdx.z;
    const float* Qg  = g_qh + (size_t)(b * NH + h) * SS * DH;
    const float* Kg  = g_kh + (size_t)(b * NH + h) * SS * DH;
    const float* Vtg = g_vt + (size_t)(b * NH + h) * DH * SS;

    const unsigned smb = (unsigned)__cvta_generic_to_shared(smu);
    const int s_cq = (tid & 15) << 2, s_rr = tid >> 4;   // 16 col-quads x 8 rows

    float o[2][8][4];
    #pragma unroll
    for (int im = 0; im < 2; im++)
        #pragma unroll
        for (int j = 0; j < 8; j++)
            #pragma unroll
            for (int r = 0; r < 4; r++) o[im][j][r] = 0.f;
    float mrow[2][2] = {{-1e30f, -1e30f}, {-1e30f, -1e30f}};
    float lrow[2][2] = {{0.f, 0.f}, {0.f, 0.f}};

#define ISSUE_TILE(K0, BUF) do {                                            \
    const unsigned kb = smb + (KS0 + (BUF) * 4352u) * 4;                    \
    const unsigned vb = smb + (VS0 + (BUF) * 4352u) * 4;                    \
    _Pragma("unroll")                                                       \
    for (int i = 0; i < 8; i++) {                                           \
        int row = s_rr + i * 8;                                             \
        CP_A16(kb + (row * 68 + s_cq) * 4,                                  \
               Kg + (size_t)((K0) + row) * DH + s_cq);                      \
        CP_A16(vb + (row * 68 + s_cq) * 4,                                  \
               Vtg + (size_t)row * SS + (K0) + s_cq);                       \
    }                                                                       \
    CP_COMMIT();                                                            \
} while (0)

    // Kick off tile 0 before Q staging (overlaps with Q LDGs)
    ISSUE_TILE(0, 0);

    // Stage Q tile (128 x 64) row-major stride 68 (tf32, producer-side cvt)
    #pragma unroll
    for (int i = 0; i < 16; i++) {
        int q = s_rr + i * 8;
        float4 v = *(const float4*)(Qg + (size_t)(q0 + q) * DH + s_cq);
        *(uint4*)&Ps[q * 68 + s_cq] = cvt4(v);
    }
    __syncthreads();

    // Hoist warp's Q fragments
    unsigned qa[2][8][4];
    {
        const unsigned qB = (wid * 32 + g) * 68 + t;
        #pragma unroll
        for (int ktd = 0; ktd < 8; ktd++)
            #pragma unroll
            for (int im = 0; im < 2; im++) {
                unsigned base = qB + im * 1088 + ktd * 8;
                qa[im][ktd][0] = Ps[base];
                qa[im][ktd][1] = Ps[base + 544];
                qa[im][ktd][2] = Ps[base + 4];
                qa[im][ktd][3] = Ps[base + 548];
            }
    }

    const unsigned pW = wid * 2176;
    const unsigned kB = g * 68 + t;

    for (int it = 0; it < SS / 64; it++) {
        const int buf = it & 1, k0 = it * 64;

        // Top barrier: all warps done computing tile it-1 (protects the
        // buffer that the next issue overwrites, and the one we convert).
        __syncthreads();
        if (it + 1 < SS / 64) {
            ISSUE_TILE((it + 1) * 64, (it + 1) & 1);
            CP_WAIT1();
        } else {
            CP_WAIT0();
        }
        __syncthreads();   // tile it's raw data visible to all

        // In-place convert pass: raw f32 -> tf32 (producer-side cvt)
        {
            unsigned* kbuf = smu + KS0 + buf * 4352;
            unsigned* vbuf = smu + VS0 + buf * 4352;
            #pragma unroll
            for (int i = 0; i < 8; i++) {
                int row = s_rr + i * 8;
                float4 kv = *(const float4*)&kbuf[row * 68 + s_cq];
                *(uint4*)&kbuf[row * 68 + s_cq] = cvt4(kv);
                float4 vv = *(const float4*)&vbuf[row * 68 + s_cq];
                *(uint4*)&vbuf[row * 68 + s_cq] = cvt4(vv);
            }
        }
        __syncthreads();   // converted tile visible

        const unsigned* Ksb  = smu + KS0 + buf * 4352;
        const unsigned* Vtsb = smu + VS0 + buf * 4352;

        // Scores: 32q x 64k per warp (pure LDS.32 fragment reads)
        float s[2][8][4];
        #pragma unroll
        for (int im = 0; im < 2; im++)
            #pragma unroll
            for (int j = 0; j < 8; j++)
                #pragma unroll
                for (int r = 0; r < 4; r++) s[im][j][r] = 0.f;

        #pragma unroll
        for (int ktd = 0; ktd < 8; ktd++) {
            #pragma unroll
            for (int nt = 0; nt < 8; nt++) {
                unsigned bk[2];
                unsigned base = kB + nt * 544 + ktd * 8;
                bk[0] = Ksb[base];
                bk[1] = Ksb[base + 4];
                mma_tf32(s[0][nt], qa[0][ktd], bk);
                mma_tf32(s[1][nt], qa[1][ktd], bk);
            }
        }

        // Scale + mask
        #pragma unroll
        for (int im = 0; im < 2; im++) {
            int r0 = q0 + wid * 32 + im * 16 + g;
            int r1 = r0 + 8;
            #pragma unroll
            for (int nt = 0; nt < 8; nt++) {
                int col = k0 + nt * 8 + t * 2;
                float2 mk0 = __ldg((const float2*)(mask + (size_t)r0 * SS + col));
                float2 mk1 = __ldg((const float2*)(mask + (size_t)r1 * SS + col));
                s[im][nt][0] = s[im][nt][0] * 0.125f - 1e9f * mk0.x;
                s[im][nt][1] = s[im][nt][1] * 0.125f - 1e9f * mk0.y;
                s[im][nt][2] = s[im][nt][2] * 0.125f - 1e9f * mk1.x;
                s[im][nt][3] = s[im][nt][3] * 0.125f - 1e9f * mk1.y;
            }
        }

        // Online softmax
        #pragma unroll
        for (int im = 0; im < 2; im++) {
            float mx0 = -1e30f, mx1 = -1e30f;
            #pragma unroll
            for (int nt = 0; nt < 8; nt++) {
                mx0 = fmaxf(mx0, fmaxf(s[im][nt][0], s[im][nt][1]));
                mx1 = fmaxf(mx1, fmaxf(s[im][nt][2], s[im][nt][3]));
            }
            mx0 = fmaxf(mx0, __shfl_xor_sync(0xffffffffu, mx0, 1));
            mx0 = fmaxf(mx0, __shfl_xor_sync(0xffffffffu, mx0, 2));
            mx1 = fmaxf(mx1, __shfl_xor_sync(0xffffffffu, mx1, 1));
            mx1 = fmaxf(mx1, __shfl_xor_sync(0xffffffffu, mx1, 2));

            float nm0 = fmaxf(mrow[im][0], mx0), nm1 = fmaxf(mrow[im][1], mx1);
            float al0 = __expf(mrow[im][0] - nm0), al1 = __expf(mrow[im][1] - nm1);
            float sum0 = 0.f, sum1 = 0.f;
            #pragma unroll
            for (int nt = 0; nt < 8; nt++) {
                float p0 = __expf(s[im][nt][0] - nm0);
                float p1 = __expf(s[im][nt][1] - nm0);
                float p2 = __expf(s[im][nt][2] - nm1);
                float p3 = __expf(s[im][nt][3] - nm1);
                s[im][nt][0] = p0; s[im][nt][1] = p1;
                s[im][nt][2] = p2; s[im][nt][3] = p3;
                sum0 += p0 + p1;
                sum1 += p2 + p3;
            }
            sum0 += __shfl_xor_sync(0xffffffffu, sum0, 1);
            sum0 += __shfl_xor_sync(0xffffffffu, sum0, 2);
            sum1 += __shfl_xor_sync(0xffffffffu, sum1, 1);
            sum1 += __shfl_xor_sync(0xffffffffu, sum1, 2);
            lrow[im][0] = lrow[im][0] * al0 + sum0;
            lrow[im][1] = lrow[im][1] * al1 + sum1;
            mrow[im][0] = nm0; mrow[im][1] = nm1;

            #pragma unroll
            for (int nt = 0; nt < 8; nt++) {
                o[im][nt][0] *= al0; o[im][nt][1] *= al0;
                o[im][nt][2] *= al1; o[im][nt][3] *= al1;
            }
        }

        // Store P (tf32) into warp's own band
        #pragma unroll
        for (int im = 0; im < 2; im++) {
            #pragma unroll
            for (int nt = 0; nt < 8; nt++) {
                unsigned idx = pW + (im * 16 + g) * 68 + nt * 8 + t * 2;
                uint2 p01 = make_uint2(tf32r(s[im][nt][0]), tf32r(s[im][nt][1]));
                *(uint2*)&Ps[idx] = p01;
                uint2 p23 = make_uint2(tf32r(s[im][nt][2]), tf32r(s[im][nt][3]));
                *(uint2*)&Ps[idx + 544] = p23;
            }
        }
        __syncwarp();

        // PV: A-frag of P, B = V^T tiles
        const unsigned pA = pW + g * 68 + t;
        #pragma unroll
        for (int ktk = 0; ktk < 8; ktk++) {
            unsigned ap[2][4];
            #pragma unroll
            for (int im = 0; im < 2; im++) {
                unsigned base = pA + im * 1088 + ktk * 8;
                ap[im][0] = Ps[base];
                ap[im][1] = Ps[base + 544];
                ap[im][2] = Ps[base + 4];
                ap[im][3] = Ps[base + 548];
            }
            #pragma unroll
            for (int ntd = 0; ntd < 8; ntd++) {
                unsigned bv[2];
                unsigned base = kB + ntd * 544 + ktk * 8;
                bv[0] = Vtsb[base];
                bv[1] = Vtsb[base + 4];
                mma_tf32(o[0][ntd], ap[0], bv);
                mma_tf32(o[1][ntd], ap[1], bv);
            }
        }
    }

    // Epilogue: normalize + write merged-head layout
    #pragma unroll
    for (int im = 0; im < 2; im++) {
        float inv0 = 1.0f / lrow[im][0], inv1 = 1.0f / lrow[im][1];
        int r0 = q0 + wid * 32 + im * 16 + g;
        int r1 = r0 + 8;
        #pragma unroll
        for (int ntd = 0; ntd < 8; ntd++) {
            int col = h * DH + ntd * 8 + t * 2;
            float2 v0 = make_float2(o[im][ntd][0] * inv0, o[im][ntd][1] * inv0);
            float2 v1 = make_float2(o[im][ntd][2] * inv1, o[im][ntd][3] * inv1);
            *(float2*)(outp + ((size_t)b * SS + r0) * DM + col) = v0;
            *(float2*)(outp + ((size_t)b * SS + r1) * DM + col) = v1;
        }
    }
#undef ISSUE_TILE
}

// ---------------------------------------------------------------------------
extern "C" void kernel_launch(void* const* d_in, const int* in_sizes, int n_in,
                              void* d_out, int out_size)
{
    const float* q    = (const float*)d_in[0];
    const float* k    = (const float*)d_in[1];
    const float* v    = (const float*)d_in[2];
    const float* mask = (const float*)d_in[3];
    const float* wq   = (const float*)d_in[4];
    const float* bq   = (const float*)d_in[5];
    const float* wk   = (const float*)d_in[6];
    const float* bk   = (const float*)d_in[7];
    const float* wv   = (const float*)d_in[8];
    const float* bv   = (const float*)d_in[9];
    const float* wo   = (const float*)d_in[10];
    const float* bo   = (const float*)d_in[11];

    float *qh, *kh, *vt, *at, *wT;
    cudaGetSymbolAddress((void**)&qh, g_qh);
    cudaGetSymbolAddress((void**)&kh, g_kh);
    cudaGetSymbolAddress((void**)&vt, g_vt);
    cudaGetSymbolAddress((void**)&at, g_at);
    cudaGetSymbolAddress((void**)&wT, g_wT);

    const int attn_smem = ATT_SMEM_U32 * (int)sizeof(unsigned);   // ~102 KB
    cudaFuncSetAttribute(attn_tf32, cudaFuncAttributeMaxDynamicSharedMemorySize,
                         attn_smem);

    // Fused weight transposes (one launch)
    dim3 tb(32, 8), tg(32, 32, 4);
    transp4<<<tg, tb>>>(wq, wk, wv, wo, wT);

    // Fused Q/K/V projections (V written transposed)
    G3 pqkv;
    pqkv.g[0] = GA{q, wT + 0 * DM * DM, bq, qh, 1};
    pqkv.g[1] = GA{k, wT + 1 * DM * DM, bk, kh, 1};
    pqkv.g[2] = GA{v, wT + 2 * DM * DM, bv, vt, 2};
    dim3 gqkv(DM / 128, MT / 128, 3);
    gemm_tf32<<<gqkv, 128>>>(pqkv);

    dim3 ga(SS / 128, NH, BB);
    attn_tf32<<<ga, 128, attn_smem>>>(mask, at);

    G3 po;
    po.g[0] = GA{at, wT + 3 * DM * DM, bo, (float*)d_out, 0};
    po.g[1] = po.g[0];
    po.g[2] = po.g[0];
    dim3 go(DM / 128, MT / 128, 1);
    gemm_tf32<<<go, 128>>>(po);
}